// round 1
// baseline (speedup 1.0000x reference)
#include <cuda_runtime.h>
#include <math.h>

// Problem constants
#define BB    16
#define CC    384
#define NTOK  1024          // 32*32
#define MTOT  (BB*NTOK)     // 16384 tokens
#define NHEAD 8
#define DH    48

// ---------------- scratch (no allocations allowed) ----------------
__device__ float g_t  [MTOT*CC];        // token-major activations [m][c]
__device__ float g_xn [MTOT*CC];        // layernorm output (reused for both LNs)
__device__ float g_qkv[MTOT*3*CC];      // qkv projection
__device__ float g_o  [MTOT*CC];        // attention output
__device__ float g_h  [MTOT*4*CC];      // mlp hidden

// ---------------- kernel 1: depthwise conv 3x3 + pos bias + layout change ----
// x: [B][C][32][32] -> g_t[(b*1024 + h*32 + w)][c] = x + conv(x) + pb[c]
__global__ void conv_prep_kernel(const float* __restrict__ x,
                                 const float* __restrict__ pw,
                                 const float* __restrict__ pb,
                                 float* __restrict__ t) {
    int idx = blockIdx.x * blockDim.x + threadIdx.x;
    if (idx >= BB * CC * NTOK) return;
    int w = idx & 31;
    int h = (idx >> 5) & 31;
    int c = (idx >> 10) % CC;
    int b = idx / (CC * NTOK);
    const float* xp = x + ((size_t)(b * CC + c) << 10);
    const float* k  = pw + c * 9;
    float acc = 0.f;
    #pragma unroll
    for (int dh = -1; dh <= 1; dh++) {
        int hh = h + dh;
        if (hh < 0 || hh > 31) continue;
        #pragma unroll
        for (int dw = -1; dw <= 1; dw++) {
            int ww = w + dw;
            if (ww < 0 || ww > 31) continue;
            acc += xp[hh * 32 + ww] * k[(dh + 1) * 3 + (dw + 1)];
        }
    }
    float v = xp[h * 32 + w] + acc + pb[c];
    t[(size_t)(b * NTOK + h * 32 + w) * CC + c] = v;
}

// ---------------- kernel 2: LayerNorm (one warp per row of 384) --------------
__global__ void ln_kernel(const float* __restrict__ in,
                          const float* __restrict__ g,
                          const float* __restrict__ bta,
                          float* __restrict__ out) {
    int warp = threadIdx.x >> 5;
    int lane = threadIdx.x & 31;
    int row  = blockIdx.x * 8 + warp;
    const float4* ip = (const float4*)(in + (size_t)row * CC);
    float4 v[3];
    #pragma unroll
    for (int i = 0; i < 3; i++) v[i] = ip[lane + 32 * i];
    float s = 0.f;
    #pragma unroll
    for (int i = 0; i < 3; i++) s += v[i].x + v[i].y + v[i].z + v[i].w;
    #pragma unroll
    for (int o = 16; o; o >>= 1) s += __shfl_xor_sync(0xffffffffu, s, o);
    float mu = s * (1.0f / CC);
    float q = 0.f;
    #pragma unroll
    for (int i = 0; i < 3; i++) {
        float a = v[i].x - mu, b2 = v[i].y - mu, c2 = v[i].z - mu, d2 = v[i].w - mu;
        q += a * a + b2 * b2 + c2 * c2 + d2 * d2;
    }
    #pragma unroll
    for (int o = 16; o; o >>= 1) q += __shfl_xor_sync(0xffffffffu, q, o);
    float r = rsqrtf(q * (1.0f / CC) + 1e-5f);
    float4* op = (float4*)(out + (size_t)row * CC);
    const float4* gp = (const float4*)g;
    const float4* bp = (const float4*)bta;
    #pragma unroll
    for (int i = 0; i < 3; i++) {
        float4 gg = gp[lane + 32 * i];
        float4 bb = bp[lane + 32 * i];
        float4 o4;
        o4.x = (v[i].x - mu) * r * gg.x + bb.x;
        o4.y = (v[i].y - mu) * r * gg.y + bb.y;
        o4.z = (v[i].z - mu) * r * gg.z + bb.z;
        o4.w = (v[i].w - mu) * r * gg.w + bb.w;
        op[lane + 32 * i] = o4;
    }
}

// ---------------- kernel 3: tiled SGEMM, C[M,N] = epi(A[M,K]@B[K,N] + bias) --
// BM=128 BN=64 BK=16, 256 threads, 8x4 per-thread tile.
__device__ __forceinline__ float gelu_exact(float x) {
    return x * normcdff(x);
}

template<bool RESID, bool GELU>
__global__ __launch_bounds__(256)
void sgemm_kernel(const float* __restrict__ A, const float* __restrict__ Bm,
                  const float* __restrict__ bias, float* __restrict__ Cm,
                  int M, int N, int K) {
    __shared__ float As[16][128];
    __shared__ float Bs[16][64];
    int tid = threadIdx.x;
    int m0 = blockIdx.y * 128;
    int n0 = blockIdx.x * 64;
    int ty = tid >> 4, tx = tid & 15;
    int arow = tid >> 2, akc = (tid & 3) << 2;
    int brow = tid >> 4, bcol = (tid & 15) << 2;
    const float* Ap = A + (size_t)(m0 + arow) * K + akc;
    const float* Bp = Bm + (size_t)brow * N + n0 + bcol;
    float acc[8][4];
    #pragma unroll
    for (int i = 0; i < 8; i++)
        #pragma unroll
        for (int j = 0; j < 4; j++) acc[i][j] = 0.f;

    for (int kt = 0; kt < K; kt += 16) {
        float4 a0 = *(const float4*)(Ap);
        float4 a1 = *(const float4*)(Ap + (size_t)64 * K);
        float4 b0 = *(const float4*)(Bp);
        As[akc + 0][arow] = a0.x; As[akc + 1][arow] = a0.y;
        As[akc + 2][arow] = a0.z; As[akc + 3][arow] = a0.w;
        As[akc + 0][arow + 64] = a1.x; As[akc + 1][arow + 64] = a1.y;
        As[akc + 2][arow + 64] = a1.z; As[akc + 3][arow + 64] = a1.w;
        *(float4*)&Bs[brow][bcol] = b0;
        __syncthreads();
        #pragma unroll
        for (int kk = 0; kk < 16; kk++) {
            float4 x0 = *(const float4*)&As[kk][ty * 8];
            float4 x1 = *(const float4*)&As[kk][ty * 8 + 4];
            float4 y0 = *(const float4*)&Bs[kk][tx * 4];
            float ar[8] = {x0.x, x0.y, x0.z, x0.w, x1.x, x1.y, x1.z, x1.w};
            float br[4] = {y0.x, y0.y, y0.z, y0.w};
            #pragma unroll
            for (int i = 0; i < 8; i++)
                #pragma unroll
                for (int j = 0; j < 4; j++) acc[i][j] += ar[i] * br[j];
        }
        __syncthreads();
        Ap += 16;
        Bp += (size_t)16 * N;
    }
    float4 bs = *(const float4*)(bias + n0 + tx * 4);
    #pragma unroll
    for (int i = 0; i < 8; i++) {
        float* cp = Cm + (size_t)(m0 + ty * 8 + i) * N + n0 + tx * 4;
        float4 r;
        r.x = acc[i][0] + bs.x;
        r.y = acc[i][1] + bs.y;
        r.z = acc[i][2] + bs.z;
        r.w = acc[i][3] + bs.w;
        if (GELU) {
            r.x = gelu_exact(r.x); r.y = gelu_exact(r.y);
            r.z = gelu_exact(r.z); r.w = gelu_exact(r.w);
        }
        if (RESID) {
            float4 old = *(const float4*)cp;
            r.x += old.x; r.y += old.y; r.z += old.z; r.w += old.w;
        }
        *(float4*)cp = r;
    }
}

// ---------------- kernel 4: flash attention -------------------------------
// BM=64 q rows per block, BN=32 kv per tile, 256 threads.
// qkv layout: row m, col s*384 + h*48 + d
__global__ __launch_bounds__(256)
void attn_kernel(const float* __restrict__ qkv, float* __restrict__ o) {
    __shared__ float Qs[64][48];
    __shared__ float Ks[32][48];
    __shared__ float Vs[32][48];
    __shared__ float Ss[64][32];

    int tid = threadIdx.x;
    int bh  = blockIdx.y;
    int b   = bh >> 3, h = bh & 7;
    int q0  = blockIdx.x * 64;
    const float scale = 0.14433756729740643f; // 48^-0.5

    const float* qbase = qkv + (size_t)(b * NTOK + q0) * (3 * CC) + h * DH;
    for (int i = tid; i < 64 * 12; i += 256) {
        int r = i / 12, c4 = i % 12;
        float4 v = *(const float4*)(qbase + (size_t)r * (3 * CC) + c4 * 4);
        v.x *= scale; v.y *= scale; v.z *= scale; v.w *= scale;
        *(float4*)&Qs[r][c4 * 4] = v;
    }

    int rrow = tid >> 2;      // phase B: 4 threads per q row
    int l4   = tid & 3;
    float m_i = -1e30f, l_i = 0.f;
    float oacc[12];
    #pragma unroll
    for (int d = 0; d < 12; d++) oacc[d] = 0.f;

    int ty = tid >> 4, tx = tid & 15; // phase A: 4 rows x 2 cols per thread

    const float* kbase = qkv + (size_t)(b * NTOK) * (3 * CC) + CC + h * DH;
    const float* vbase = kbase + CC;
    __syncthreads();

    for (int kt = 0; kt < 32; kt++) {
        int k0 = kt * 32;
        for (int i = tid; i < 768; i += 256) {
            int which = (i >= 384);
            int j = which ? i - 384 : i;
            int r = j / 12, c4 = j % 12;
            const float* src = (which ? vbase : kbase) + (size_t)(k0 + r) * (3 * CC) + c4 * 4;
            float4 v = *(const float4*)src;
            if (which) *(float4*)&Vs[r][c4 * 4] = v;
            else       *(float4*)&Ks[r][c4 * 4] = v;
        }
        __syncthreads();

        // S = Qs @ Ks^T (already scaled)
        float s[4][2];
        #pragma unroll
        for (int i = 0; i < 4; i++) { s[i][0] = 0.f; s[i][1] = 0.f; }
        #pragma unroll
        for (int kk = 0; kk < 48; kk += 4) {
            float4 qv[4], kv2[2];
            #pragma unroll
            for (int i = 0; i < 4; i++) qv[i] = *(const float4*)&Qs[4 * ty + i][kk];
            #pragma unroll
            for (int j = 0; j < 2; j++) kv2[j] = *(const float4*)&Ks[2 * tx + j][kk];
            #pragma unroll
            for (int i = 0; i < 4; i++)
                #pragma unroll
                for (int j = 0; j < 2; j++)
                    s[i][j] += qv[i].x * kv2[j].x + qv[i].y * kv2[j].y +
                               qv[i].z * kv2[j].z + qv[i].w * kv2[j].w;
        }
        #pragma unroll
        for (int i = 0; i < 4; i++) {
            Ss[4 * ty + i][2 * tx + 0] = s[i][0];
            Ss[4 * ty + i][2 * tx + 1] = s[i][1];
        }
        __syncthreads();

        // online softmax for row rrow, cols l4*8 .. +7
        float4 p0 = *(const float4*)&Ss[rrow][l4 * 8];
        float4 p1 = *(const float4*)&Ss[rrow][l4 * 8 + 4];
        float tm = fmaxf(fmaxf(fmaxf(p0.x, p0.y), fmaxf(p0.z, p0.w)),
                         fmaxf(fmaxf(p1.x, p1.y), fmaxf(p1.z, p1.w)));
        tm = fmaxf(tm, __shfl_xor_sync(0xffffffffu, tm, 1));
        tm = fmaxf(tm, __shfl_xor_sync(0xffffffffu, tm, 2));
        float newm = fmaxf(m_i, tm);
        float alpha = __expf(m_i - newm);
        p0.x = __expf(p0.x - newm); p0.y = __expf(p0.y - newm);
        p0.z = __expf(p0.z - newm); p0.w = __expf(p0.w - newm);
        p1.x = __expf(p1.x - newm); p1.y = __expf(p1.y - newm);
        p1.z = __expf(p1.z - newm); p1.w = __expf(p1.w - newm);
        float rs = p0.x + p0.y + p0.z + p0.w + p1.x + p1.y + p1.z + p1.w;
        rs += __shfl_xor_sync(0xffffffffu, rs, 1);
        rs += __shfl_xor_sync(0xffffffffu, rs, 2);
        l_i = l_i * alpha + rs;
        m_i = newm;
        #pragma unroll
        for (int d = 0; d < 12; d++) oacc[d] *= alpha;
        *(float4*)&Ss[rrow][l4 * 8]     = p0;
        *(float4*)&Ss[rrow][l4 * 8 + 4] = p1;
        __syncwarp();

        // O += P @ V (12 d-values per thread)
        #pragma unroll 4
        for (int j = 0; j < 32; j++) {
            float p = Ss[rrow][j];
            float4 v0 = *(const float4*)&Vs[j][l4 * 12];
            float4 v1 = *(const float4*)&Vs[j][l4 * 12 + 4];
            float4 v2 = *(const float4*)&Vs[j][l4 * 12 + 8];
            oacc[0] += p * v0.x; oacc[1] += p * v0.y; oacc[2]  += p * v0.z; oacc[3]  += p * v0.w;
            oacc[4] += p * v1.x; oacc[5] += p * v1.y; oacc[6]  += p * v1.z; oacc[7]  += p * v1.w;
            oacc[8] += p * v2.x; oacc[9] += p * v2.y; oacc[10] += p * v2.z; oacc[11] += p * v2.w;
        }
        __syncthreads();
    }

    float inv = 1.f / l_i;
    float* op = o + (size_t)(b * NTOK + q0 + rrow) * CC + h * DH + l4 * 12;
    float4 w0 = make_float4(oacc[0] * inv, oacc[1] * inv, oacc[2] * inv, oacc[3] * inv);
    float4 w1 = make_float4(oacc[4] * inv, oacc[5] * inv, oacc[6] * inv, oacc[7] * inv);
    float4 w2 = make_float4(oacc[8] * inv, oacc[9] * inv, oacc[10] * inv, oacc[11] * inv);
    *(float4*)(op + 0) = w0;
    *(float4*)(op + 4) = w1;
    *(float4*)(op + 8) = w2;
}

// ---------------- kernel 5: final transpose to NCHW -----------------------
// g_t[(b*1024+n)][c] -> out[b][c][n]
__global__ void transpose_kernel(const float* __restrict__ t, float* __restrict__ out) {
    __shared__ float tile[32][33];
    int b  = blockIdx.z;
    int n0 = blockIdx.x * 32;
    int c0 = blockIdx.y * 32;
    int tx = threadIdx.x, ty = threadIdx.y;
    #pragma unroll
    for (int i = 0; i < 4; i++)
        tile[ty + 8 * i][tx] = t[(size_t)(b * NTOK + n0 + ty + 8 * i) * CC + c0 + tx];
    __syncthreads();
    #pragma unroll
    for (int i = 0; i < 4; i++)
        out[(size_t)(b * CC + c0 + ty + 8 * i) * NTOK + n0 + tx] = tile[tx][ty + 8 * i];
}

// ---------------- launch ----------------------------------------------------
extern "C" void kernel_launch(void* const* d_in, const int* in_sizes, int n_in,
                              void* d_out, int out_size) {
    const float* x     = (const float*)d_in[0];
    const float* pos_w = (const float*)d_in[1];
    const float* pos_b = (const float*)d_in[2];
    const float* g1    = (const float*)d_in[3];
    const float* b1    = (const float*)d_in[4];
    const float* wqkv  = (const float*)d_in[5];
    const float* bqkv  = (const float*)d_in[6];
    const float* wproj = (const float*)d_in[7];
    const float* bproj = (const float*)d_in[8];
    const float* g2    = (const float*)d_in[9];
    const float* b2    = (const float*)d_in[10];
    const float* w1    = (const float*)d_in[11];
    const float* bf1   = (const float*)d_in[12];
    const float* w2    = (const float*)d_in[13];
    const float* bf2   = (const float*)d_in[14];
    float* out = (float*)d_out;

    float *t, *xn, *qkv, *o, *hbuf;
    cudaGetSymbolAddress((void**)&t,    g_t);
    cudaGetSymbolAddress((void**)&xn,   g_xn);
    cudaGetSymbolAddress((void**)&qkv,  g_qkv);
    cudaGetSymbolAddress((void**)&o,    g_o);
    cudaGetSymbolAddress((void**)&hbuf, g_h);

    // 1) conv + pos bias -> t[m][c]
    {
        int total = BB * CC * NTOK;
        conv_prep_kernel<<<(total + 255) / 256, 256>>>(x, pos_w, pos_b, t);
    }
    // 2) LN1: t -> xn
    ln_kernel<<<MTOT / 8, 256>>>(t, g1, b1, xn);
    // 3) qkv = xn @ wqkv + bqkv
    sgemm_kernel<false, false><<<dim3(3 * CC / 64, MTOT / 128), 256>>>(
        xn, wqkv, bqkv, qkv, MTOT, 3 * CC, CC);
    // 4) attention -> o
    attn_kernel<<<dim3(NTOK / 64, BB * NHEAD), 256>>>(qkv, o);
    // 5) t += o @ wproj + bproj
    sgemm_kernel<true, false><<<dim3(CC / 64, MTOT / 128), 256>>>(
        o, wproj, bproj, t, MTOT, CC, CC);
    // 6) LN2: t -> xn
    ln_kernel<<<MTOT / 8, 256>>>(t, g2, b2, xn);
    // 7) h = gelu(xn @ w1 + bf1)
    sgemm_kernel<false, true><<<dim3(4 * CC / 64, MTOT / 128), 256>>>(
        xn, w1, bf1, hbuf, MTOT, 4 * CC, CC);
    // 8) t += h @ w2 + bf2
    sgemm_kernel<true, false><<<dim3(CC / 64, MTOT / 128), 256>>>(
        hbuf, w2, bf2, t, MTOT, CC, 4 * CC);
    // 9) transpose to NCHW
    transpose_kernel<<<dim3(NTOK / 32, CC / 32, BB), dim3(32, 8)>>>(t, out);
}